// round 7
// baseline (speedup 1.0000x reference)
#include <cuda_runtime.h>
#include <cuda_bf16.h>
#include <cstdint>

#define BB 32
#define TT 168
#define SS 32      // N_HYDRO stations
#define NM 64      // meteo nodes
#define NN 96      // total nodes
#define EE 384     // edges
#define HG 64      // HID_GNN
#define HH 128     // HID_LSTM
#define G4 512     // 4*HH gates
#define FUT 24
#define GG (BB*TT) // 5376 graphs

// ---------------- device scratch (allocation-free rule: __device__ globals) ----
__device__ float4 g_Whh4[SS*32*G4];                 // [s][k4][j]
__device__ float  g_WihT[SS*HG*G4];                 // [s][k][j]
__device__ float  g_bsum[SS*G4];                    // bih + bhh
__device__ float  g_feat[(size_t)SS*GG*HG];         // [s][g][k]
__device__ float  g_Gin [(size_t)SS*GG*G4];         // [s][g][j]

// ---------------- packed fp32x2 helpers (sm_100+) ------------------------------
__device__ __forceinline__ void ffma2(unsigned long long &d, unsigned long long a, unsigned long long b) {
    asm("fma.rn.f32x2 %0, %1, %2, %0;" : "+l"(d) : "l"(a), "l"(b));
}
__device__ __forceinline__ float2 unpack2(unsigned long long v) {
    float2 r; asm("mov.b64 {%0,%1}, %2;" : "=f"(r.x), "=f"(r.y) : "l"(v)); return r;
}
__device__ __forceinline__ unsigned long long pack2(float x, float y) {
    unsigned long long r; asm("mov.b64 %0, {%1,%2};" : "=l"(r) : "f"(x), "f"(y)); return r;
}
__device__ __forceinline__ float lrelu(float v) { return v > 0.f ? v : 0.01f*v; }
__device__ __forceinline__ float fast_sig(float x)  { return __fdividef(1.f, 1.f + __expf(-x)); }
__device__ __forceinline__ float fast_tanh(float x) { return 1.f - __fdividef(2.f, 1.f + __expf(2.f*x)); }

// ================== K0: weight repack =========================================
__global__ void k0_prep(const float* __restrict__ Wih, const float* __restrict__ Whh,
                        const float* __restrict__ bih, const float* __restrict__ bhh) {
    int i = blockIdx.x*blockDim.x + threadIdx.x;
    if (i < SS*32*G4) {
        int s = i / (32*G4); int r = i % (32*G4); int k4 = r / G4; int j = r % G4;
        const float* w = Whh + (size_t)(s*G4 + j)*HH + k4*4;
        g_Whh4[i] = make_float4(w[0], w[1], w[2], w[3]);
    }
    if (i < SS*HG*G4) {
        int s = i / (HG*G4); int r = i % (HG*G4); int k = r / G4; int j = r % G4;
        g_WihT[i] = Wih[(size_t)(s*G4 + j)*HG + k];
    }
    if (i < SS*G4) g_bsum[i] = bih[i] + bhh[i];
}

// ================== K1: GNN scalars -> 64-d hydro features ====================
__global__ void k1_feat(const float* __restrict__ hydro, const float* __restrict__ meteo,
                        const int* __restrict__ edges32,
                        const float* __restrict__ Wroot, const float* __restrict__ Wrel,
                        const float* __restrict__ bgnn) {
    __shared__ float xs[NN];
    __shared__ float agg[SS];
    __shared__ int   is64;
    int g = blockIdx.x;
    int tid = threadIdx.x;
    if (tid == 0) is64 = 1;
    if (tid < NN) xs[tid] = (tid < SS) ? hydro[(size_t)g*SS + tid]
                                       : meteo[(size_t)g*NM + (tid - SS)];
    if (tid < SS) agg[tid] = 0.f;
    __syncthreads();
    for (int e = tid; e < 2*EE; e += blockDim.x) {
        if ((e & 1) && edges32[e] != 0) atomicExch(&is64, 0);
    }
    __syncthreads();
    const int stride = is64 ? 2 : 1;
    const int dstOff = is64 ? 2*EE : EE;
    for (int e = tid; e < EE; e += blockDim.x) {
        int dst = edges32[dstOff + e*stride];
        if (dst >= 0 && dst < SS) {
            int src = edges32[e*stride];
            if (src >= 0 && src < NN) atomicAdd(&agg[dst], xs[src]);
        }
    }
    __syncthreads();
    for (int i = tid; i < SS*HG; i += blockDim.x) {
        int s = i >> 6; int k = i & 63;
        float v = xs[s]*Wroot[k] + agg[s]*Wrel[k] + bgnn[k];
        g_feat[((size_t)s*GG + g)*HG + k] = lrelu(v);
    }
}

// ================== K2: input GEMM  Gin = feat @ WihT + bsum ==================
__global__ __launch_bounds__(256) void k2_gemm() {
    extern __shared__ float sm2[];
    float* As = sm2;                 // [64][66]
    float* Bs = sm2 + 64*66;         // [64][128]
    int s = blockIdx.z, g0 = blockIdx.x*64, j0 = blockIdx.y*128;
    int tid = threadIdx.x;

    const float4* fa = (const float4*)(g_feat + ((size_t)s*GG + g0)*HG);
    for (int i = tid; i < 64*16; i += 256) {
        int r = i >> 4, k4 = i & 15;
        float4 v = fa[r*16 + k4];
        float* d = As + r*66 + k4*4;
        d[0]=v.x; d[1]=v.y; d[2]=v.z; d[3]=v.w;
    }
    for (int i = tid; i < 64*32; i += 256) {
        int k = i >> 5, q = i & 31;
        float4 v = *(const float4*)(g_WihT + ((size_t)(s*HG + k))*G4 + j0 + q*4);
        *(float4*)(Bs + k*128 + q*4) = v;
    }
    __syncthreads();

    int ty = tid >> 4, tx = tid & 15;
    unsigned long long acc[4][4];
    #pragma unroll
    for (int i = 0; i < 4; i++)
        #pragma unroll
        for (int q = 0; q < 4; q++) acc[i][q] = 0ull;

    #pragma unroll 8
    for (int k = 0; k < 64; k++) {
        const unsigned long long* bp = (const unsigned long long*)(Bs + k*128 + tx*8);
        unsigned long long b0 = bp[0], b1 = bp[1], b2 = bp[2], b3 = bp[3];
        #pragma unroll
        for (int i = 0; i < 4; i++) {
            float a = As[(ty*4 + i)*66 + k];
            unsigned long long a2 = pack2(a, a);
            ffma2(acc[i][0], a2, b0);
            ffma2(acc[i][1], a2, b1);
            ffma2(acc[i][2], a2, b2);
            ffma2(acc[i][3], a2, b3);
        }
    }
    const float* bs = g_bsum + s*G4 + j0 + tx*8;
    #pragma unroll
    for (int i = 0; i < 4; i++) {
        int g = g0 + ty*4 + i;
        float* orow = g_Gin + ((size_t)s*GG + g)*G4 + j0 + tx*8;
        #pragma unroll
        for (int q = 0; q < 4; q++) {
            float2 v = unpack2(acc[i][q]);
            float2 o; o.x = v.x + bs[2*q]; o.y = v.y + bs[2*q+1];
            *(float2*)(orow + 2*q) = o;
        }
    }
}

// ================== K3: recurrent LSTM + head =================================
// 128 blocks = (station, 8-batch group). 512 threads: thread owns gate row j=tid
// for all 8 batches. Weight row halves: k<64 in 64 REGISTERS (loop-invariant!),
// k>=64 in smem [16][512] float4 (128KB). h double-buffered in smem; gate
// activations staged in smem for the (m,bi)-owner state update.
__global__ __launch_bounds__(512, 1) void k3_lstm(const float* __restrict__ Wlin,
                                                  const float* __restrict__ blin,
                                                  float* __restrict__ out) {
    extern __shared__ char sm3[];
    float4* wsm  = (float4*)sm3;                      // [16][512] : 131072 B
    float*  hbuf = (float*)(sm3 + 131072);            // 2 x [8][128] : 8192 B
    float*  gact = (float*)(sm3 + 131072 + 8192);     // [8][512] : 16384 B

    const int tid = threadIdx.x;
    const int s  = blockIdx.x >> 2;
    const int b0 = (blockIdx.x & 3) * 8;
    const int j  = tid;

    const float4* gw4 = g_Whh4 + (size_t)s*32*G4;
    // smem half of weights: k4 = 16..31, layout [k4-16][j]
    for (int i = tid; i < 16*512; i += 512) {
        int k4 = i >> 9, jj = i & 511;
        wsm[i] = gw4[(16 + k4)*G4 + jj];
    }
    // register half: k4 = 0..15 (64 weights, 64 registers; loop fully unrolled)
    const ulonglong2* gww = (const ulonglong2*)gw4;
    ulonglong2 wr[16];
    #pragma unroll
    for (int k4 = 0; k4 < 16; k4++) wr[k4] = gww[k4*G4 + j];

    for (int i = tid; i < 2*8*HH; i += 512) hbuf[i] = 0.f;
    __syncthreads();

    const bool isG = (j >= 256) && (j < 384);          // g-gate rows -> tanh
    // state-update ownership: pairs p0=2*tid, p0+1 -> unit m0,m0+1 of batch p0>>7
    const int m0  = (2*tid) & 127;
    const int ub  = (2*tid) >> 7;
    float c0 = 0.f, c1 = 0.f;

    const float* ginb = g_Gin + ((size_t)s*GG + (size_t)b0*TT)*G4 + j;
    const ulonglong2* wsp = (const ulonglong2*)wsm + j;
    float* hr = hbuf;          // read buffer
    float* hw = hbuf + 1024;   // write buffer

    for (int t = 0; t < TT; t++) {
        // Gin prefetch (DRAM latency hidden behind the k-loop)
        const float* gp = ginb + (size_t)t*G4;
        float gin[8];
        #pragma unroll
        for (int bi = 0; bi < 8; bi++) gin[bi] = gp[(size_t)bi*TT*G4];

        unsigned long long acc[8];
        #pragma unroll
        for (int bi = 0; bi < 8; bi++) acc[bi] = 0ull;

        const ulonglong2* hp = (const ulonglong2*)hr;   // [8][32]
        // ---- k 0..63 : weights from registers ----
        #pragma unroll
        for (int k4 = 0; k4 < 16; k4++) {
            ulonglong2 w = wr[k4];
            #pragma unroll
            for (int bi = 0; bi < 8; bi++) {
                ulonglong2 h4 = hp[bi*32 + k4];
                ffma2(acc[bi], w.x, h4.x);
                ffma2(acc[bi], w.y, h4.y);
            }
        }
        // ---- k 64..127 : weights from smem ----
        #pragma unroll 4
        for (int k4 = 16; k4 < 32; k4++) {
            ulonglong2 w = wsp[(k4 - 16)*512];
            #pragma unroll
            for (int bi = 0; bi < 8; bi++) {
                ulonglong2 h4 = hp[bi*32 + k4];
                ffma2(acc[bi], w.x, h4.x);
                ffma2(acc[bi], w.y, h4.y);
            }
        }
        // activations for this gate row
        #pragma unroll
        for (int bi = 0; bi < 8; bi++) {
            float2 v = unpack2(acc[bi]);
            float pre = v.x + v.y + gin[bi];
            gact[bi*G4 + j] = isG ? fast_tanh(pre) : fast_sig(pre);
        }
        __syncthreads();
        // state update: thread owns units (m0, m0+1) of batch ub
        {
            const float* ga = gact + ub*G4;
            float2 iv = *(const float2*)(ga + m0);
            float2 fv = *(const float2*)(ga + 128 + m0);
            float2 gv = *(const float2*)(ga + 256 + m0);
            float2 ov = *(const float2*)(ga + 384 + m0);
            c0 = fv.x*c0 + iv.x*gv.x;
            c1 = fv.y*c1 + iv.y*gv.y;
            float2 hn; hn.x = ov.x*fast_tanh(c0); hn.y = ov.y*fast_tanh(c1);
            *(float2*)(hw + ub*HH + m0) = hn;
        }
        __syncthreads();
        float* tmp = hr; hr = hw; hw = tmp;
    }

    // head: pred[b][s][f] = lrelu(h . Wlin[f] + blin[f]) ; final h is in hr
    for (int i = tid; i < 8*FUT; i += 512) {
        int bi = i / FUT, f = i % FUT;
        const float* hrow = hr + bi*HH;
        const float* wrow = Wlin + f*HH;
        float acc = 0.f;
        #pragma unroll 8
        for (int m = 0; m < HH; m++) acc += hrow[m]*wrow[m];
        acc += blin[f];
        out[((size_t)(b0 + bi)*SS + s)*FUT + f] = lrelu(acc);
    }
}

// ================== launch =====================================================
extern "C" void kernel_launch(void* const* d_in, const int* in_sizes, int n_in,
                              void* d_out, int out_size) {
    const float* meteo = (const float*)d_in[0];
    const float* hydro = (const float*)d_in[1];
    const int*   edges = (const int*)d_in[2];
    const float* Wroot = (const float*)d_in[3];
    const float* Wrel  = (const float*)d_in[4];
    const float* bgnn  = (const float*)d_in[5];
    const float* Wih   = (const float*)d_in[6];
    const float* Whh   = (const float*)d_in[7];
    const float* bih   = (const float*)d_in[8];
    const float* bhh   = (const float*)d_in[9];
    const float* Wlin  = (const float*)d_in[10];
    const float* blin  = (const float*)d_in[11];
    float* out = (float*)d_out;

    static_assert(GG == 84*64, "g tiling");

    const int smem2 = (64*66 + 64*128) * (int)sizeof(float);      // 49664
    const int smem3 = 131072 + 8192 + 16384;                      // 155648
    cudaFuncSetAttribute(k2_gemm, cudaFuncAttributeMaxDynamicSharedMemorySize, smem2);
    cudaFuncSetAttribute(k3_lstm, cudaFuncAttributeMaxDynamicSharedMemorySize, smem3);

    k0_prep<<<(SS*HG*G4 + 255)/256, 256>>>(Wih, Whh, bih, bhh);
    k1_feat<<<GG, 256>>>(hydro, meteo, edges, Wroot, Wrel, bgnn);
    k2_gemm<<<dim3(84, 4, SS), 256, smem2>>>();
    k3_lstm<<<SS*4, 256 /*unused*/ + 256, smem3>>>(Wlin, blin, out);
}

// round 8
// speedup vs baseline: 1.4724x; 1.4724x over previous
#include <cuda_runtime.h>
#include <cuda_bf16.h>
#include <cstdint>

#define BB 32
#define TT 168
#define SS 32      // N_HYDRO stations
#define NM 64      // meteo nodes
#define NN 96      // total nodes
#define EE 384     // edges
#define HG 64      // HID_GNN
#define HH 128     // HID_LSTM
#define G4 512     // 4*HH gates
#define FUT 24
#define GG (BB*TT) // 5376 graphs

// ---------------- device scratch (allocation-free rule: __device__ globals) ----
__device__ float4 g_Whh4[SS*32*G4];                 // [s][k4][j]
__device__ float  g_WihT[SS*HG*G4];                 // [s][k][j]
__device__ float  g_bsum[SS*G4];                    // bih + bhh
__device__ float  g_feat[(size_t)SS*GG*HG];         // [s][g][k]
__device__ float  g_Gin [(size_t)SS*GG*G4];         // [s][g][j]

// ---------------- packed fp32x2 helpers (sm_100+) ------------------------------
__device__ __forceinline__ void ffma2(unsigned long long &d, unsigned long long a, unsigned long long b) {
    asm("fma.rn.f32x2 %0, %1, %2, %0;" : "+l"(d) : "l"(a), "l"(b));
}
__device__ __forceinline__ float2 unpack2(unsigned long long v) {
    float2 r; asm("mov.b64 {%0,%1}, %2;" : "=f"(r.x), "=f"(r.y) : "l"(v)); return r;
}
__device__ __forceinline__ unsigned long long pack2(float x, float y) {
    unsigned long long r; asm("mov.b64 %0, {%1,%2};" : "=l"(r) : "f"(x), "f"(y)); return r;
}
__device__ __forceinline__ float lrelu(float v) { return v > 0.f ? v : 0.01f*v; }
__device__ __forceinline__ float fast_sig(float x)  { return __fdividef(1.f, 1.f + __expf(-x)); }
__device__ __forceinline__ float fast_tanh(float x) { return 1.f - __fdividef(2.f, 1.f + __expf(2.f*x)); }

// ================== K0: weight repack =========================================
__global__ void k0_prep(const float* __restrict__ Wih, const float* __restrict__ Whh,
                        const float* __restrict__ bih, const float* __restrict__ bhh) {
    int i = blockIdx.x*blockDim.x + threadIdx.x;
    if (i < SS*32*G4) {
        int s = i / (32*G4); int r = i % (32*G4); int k4 = r / G4; int j = r % G4;
        const float* w = Whh + (size_t)(s*G4 + j)*HH + k4*4;
        g_Whh4[i] = make_float4(w[0], w[1], w[2], w[3]);
    }
    if (i < SS*HG*G4) {
        int s = i / (HG*G4); int r = i % (HG*G4); int k = r / G4; int j = r % G4;
        g_WihT[i] = Wih[(size_t)(s*G4 + j)*HG + k];
    }
    if (i < SS*G4) g_bsum[i] = bih[i] + bhh[i];
}

// ================== K1: GNN scalars -> 64-d hydro features ====================
__global__ void k1_feat(const float* __restrict__ hydro, const float* __restrict__ meteo,
                        const int* __restrict__ edges32,
                        const float* __restrict__ Wroot, const float* __restrict__ Wrel,
                        const float* __restrict__ bgnn) {
    __shared__ float xs[NN];
    __shared__ float agg[SS];
    __shared__ int   is64;
    int g = blockIdx.x;
    int tid = threadIdx.x;
    if (tid == 0) is64 = 1;
    if (tid < NN) xs[tid] = (tid < SS) ? hydro[(size_t)g*SS + tid]
                                       : meteo[(size_t)g*NM + (tid - SS)];
    if (tid < SS) agg[tid] = 0.f;
    __syncthreads();
    for (int e = tid; e < 2*EE; e += blockDim.x) {
        if ((e & 1) && edges32[e] != 0) atomicExch(&is64, 0);
    }
    __syncthreads();
    const int stride = is64 ? 2 : 1;
    const int dstOff = is64 ? 2*EE : EE;
    for (int e = tid; e < EE; e += blockDim.x) {
        int dst = edges32[dstOff + e*stride];
        if (dst >= 0 && dst < SS) {
            int src = edges32[e*stride];
            if (src >= 0 && src < NN) atomicAdd(&agg[dst], xs[src]);
        }
    }
    __syncthreads();
    for (int i = tid; i < SS*HG; i += blockDim.x) {
        int s = i >> 6; int k = i & 63;
        float v = xs[s]*Wroot[k] + agg[s]*Wrel[k] + bgnn[k];
        g_feat[((size_t)s*GG + g)*HG + k] = lrelu(v);
    }
}

// ================== K2: input GEMM  Gin = feat @ WihT + bsum ==================
__global__ __launch_bounds__(256) void k2_gemm() {
    extern __shared__ float sm2[];
    float* As = sm2;                 // [64][66]
    float* Bs = sm2 + 64*66;         // [64][128]
    int s = blockIdx.z, g0 = blockIdx.x*64, j0 = blockIdx.y*128;
    int tid = threadIdx.x;

    const float4* fa = (const float4*)(g_feat + ((size_t)s*GG + g0)*HG);
    for (int i = tid; i < 64*16; i += 256) {
        int r = i >> 4, k4 = i & 15;
        float4 v = fa[r*16 + k4];
        float* d = As + r*66 + k4*4;
        d[0]=v.x; d[1]=v.y; d[2]=v.z; d[3]=v.w;
    }
    for (int i = tid; i < 64*32; i += 256) {
        int k = i >> 5, q = i & 31;
        float4 v = *(const float4*)(g_WihT + ((size_t)(s*HG + k))*G4 + j0 + q*4);
        *(float4*)(Bs + k*128 + q*4) = v;
    }
    __syncthreads();

    int ty = tid >> 4, tx = tid & 15;
    unsigned long long acc[4][4];
    #pragma unroll
    for (int i = 0; i < 4; i++)
        #pragma unroll
        for (int q = 0; q < 4; q++) acc[i][q] = 0ull;

    #pragma unroll 8
    for (int k = 0; k < 64; k++) {
        const unsigned long long* bp = (const unsigned long long*)(Bs + k*128 + tx*8);
        unsigned long long b0 = bp[0], b1 = bp[1], b2 = bp[2], b3 = bp[3];
        #pragma unroll
        for (int i = 0; i < 4; i++) {
            float a = As[(ty*4 + i)*66 + k];
            unsigned long long a2 = pack2(a, a);
            ffma2(acc[i][0], a2, b0);
            ffma2(acc[i][1], a2, b1);
            ffma2(acc[i][2], a2, b2);
            ffma2(acc[i][3], a2, b3);
        }
    }
    const float* bs = g_bsum + s*G4 + j0 + tx*8;
    #pragma unroll
    for (int i = 0; i < 4; i++) {
        int g = g0 + ty*4 + i;
        float* orow = g_Gin + ((size_t)s*GG + g)*G4 + j0 + tx*8;
        #pragma unroll
        for (int q = 0; q < 4; q++) {
            float2 v = unpack2(acc[i][q]);
            float2 o; o.x = v.x + bs[2*q]; o.y = v.y + bs[2*q+1];
            *(float2*)(orow + 2*q) = o;
        }
    }
}

// ================== K3: recurrent LSTM + head =================================
// 128 blocks = (station, 8-batch group). 1024 threads, k-split:
//   thread (j = tid&511, kh = tid>>9) owns gate row j over k in [64*kh, 64*kh+64).
//   Weight half-row = 16 ulonglong2 = 32 REGISTERS. NO weight smem at all.
//   kh=1 threads store reduced partials; kh=0 threads add gin + activations;
//   kh=1 threads own cell state + h update. 3 barriers/step. smem = 40KB.
__global__ __launch_bounds__(1024, 1) void k3_lstm(const float* __restrict__ Wlin,
                                                   const float* __restrict__ blin,
                                                   float* __restrict__ out) {
    extern __shared__ float sm3[];
    float* hbuf = sm3;                    // 2 x [8][128] = 2048 floats
    float* gact = sm3 + 2048;             // [8][512]    = 4096 floats
    float* part = sm3 + 2048 + 4096;      // [8][512]    = 4096 floats

    const int tid = threadIdx.x;
    const int j   = tid & 511;
    const int kh  = tid >> 9;             // 0 or 1 (uniform per warp)
    const int s   = blockIdx.x >> 2;
    const int b0  = (blockIdx.x & 3) * 8;

    // weight half-row in registers (loop-invariant across all 168 steps)
    const ulonglong2* gww = (const ulonglong2*)(g_Whh4 + (size_t)s*32*G4);
    ulonglong2 wr[16];
    #pragma unroll
    for (int kk = 0; kk < 16; kk++) wr[kk] = gww[(kh*16 + kk)*G4 + j];

    for (int i = tid; i < 2*8*HH; i += 1024) hbuf[i] = 0.f;
    __syncthreads();

    const bool isG = (j >= 256) && (j < 384);      // g-gate rows -> tanh
    // kh=1 threads: state-update ownership (units m0,m0+1 of batch ub)
    const int m0 = (2*j) & 127;
    const int ub = (2*j) >> 7;
    float c0 = 0.f, c1 = 0.f;

    const float* ginb = g_Gin + ((size_t)s*GG + (size_t)b0*TT)*G4 + j;
    float* hr = hbuf;
    float* hw = hbuf + 1024;

    for (int t = 0; t < TT; t++) {
        // gin prefetch (kh=0 only; latency hidden behind the FMA section)
        float gin[8];
        if (kh == 0) {
            const float* gp = ginb + (size_t)t*G4;
            #pragma unroll
            for (int bi = 0; bi < 8; bi++) gin[bi] = gp[(size_t)bi*TT*G4];
        }

        unsigned long long acc[8];
        #pragma unroll
        for (int bi = 0; bi < 8; bi++) acc[bi] = 0ull;

        const ulonglong2* hp = (const ulonglong2*)hr + kh*16;   // [8][32] + half offset
        #pragma unroll 4
        for (int kk = 0; kk < 16; kk++) {
            ulonglong2 w = wr[kk];
            #pragma unroll
            for (int bi = 0; bi < 8; bi++) {
                ulonglong2 h4 = hp[bi*32 + kk];
                ffma2(acc[bi], w.x, h4.x);
                ffma2(acc[bi], w.y, h4.y);
            }
        }
        if (kh == 1) {
            #pragma unroll
            for (int bi = 0; bi < 8; bi++) {
                float2 v = unpack2(acc[bi]);
                part[bi*G4 + j] = v.x + v.y;
            }
        }
        __syncthreads();                     // partials visible
        if (kh == 0) {
            #pragma unroll
            for (int bi = 0; bi < 8; bi++) {
                float2 v = unpack2(acc[bi]);
                float pre = v.x + v.y + part[bi*G4 + j] + gin[bi];
                gact[bi*G4 + j] = isG ? fast_tanh(pre) : fast_sig(pre);
            }
        }
        __syncthreads();                     // gact ready
        if (kh == 1) {
            const float* ga = gact + ub*G4;
            float2 iv = *(const float2*)(ga + m0);
            float2 fv = *(const float2*)(ga + 128 + m0);
            float2 gv = *(const float2*)(ga + 256 + m0);
            float2 ov = *(const float2*)(ga + 384 + m0);
            c0 = fv.x*c0 + iv.x*gv.x;
            c1 = fv.y*c1 + iv.y*gv.y;
            float2 hn; hn.x = ov.x*fast_tanh(c0); hn.y = ov.y*fast_tanh(c1);
            *(float2*)(hw + ub*HH + m0) = hn;
        }
        __syncthreads();                     // h(t+1) ready
        float* tmp = hr; hr = hw; hw = tmp;
    }

    // head: pred[b][s][f] = lrelu(h . Wlin[f] + blin[f]) ; final h is in hr
    for (int i = tid; i < 8*FUT; i += 1024) {
        int bi = i / FUT, f = i % FUT;
        const float* hrow = hr + bi*HH;
        const float* wrow = Wlin + f*HH;
        float acc = 0.f;
        #pragma unroll 8
        for (int m = 0; m < HH; m++) acc += hrow[m]*wrow[m];
        acc += blin[f];
        out[((size_t)(b0 + bi)*SS + s)*FUT + f] = lrelu(acc);
    }
}

// ================== launch =====================================================
extern "C" void kernel_launch(void* const* d_in, const int* in_sizes, int n_in,
                              void* d_out, int out_size) {
    const float* meteo = (const float*)d_in[0];
    const float* hydro = (const float*)d_in[1];
    const int*   edges = (const int*)d_in[2];
    const float* Wroot = (const float*)d_in[3];
    const float* Wrel  = (const float*)d_in[4];
    const float* bgnn  = (const float*)d_in[5];
    const float* Wih   = (const float*)d_in[6];
    const float* Whh   = (const float*)d_in[7];
    const float* bih   = (const float*)d_in[8];
    const float* bhh   = (const float*)d_in[9];
    const float* Wlin  = (const float*)d_in[10];
    const float* blin  = (const float*)d_in[11];
    float* out = (float*)d_out;

    static_assert(GG == 84*64, "g tiling");

    const int smem2 = (64*66 + 64*128) * (int)sizeof(float);      // 49664
    const int smem3 = (2048 + 4096 + 4096) * (int)sizeof(float);  // 40960
    cudaFuncSetAttribute(k2_gemm, cudaFuncAttributeMaxDynamicSharedMemorySize, smem2);
    cudaFuncSetAttribute(k3_lstm, cudaFuncAttributeMaxDynamicSharedMemorySize, smem3);

    k0_prep<<<(SS*HG*G4 + 255)/256, 256>>>(Wih, Whh, bih, bhh);
    k1_feat<<<GG, 256>>>(hydro, meteo, edges, Wroot, Wrel, bgnn);
    k2_gemm<<<dim3(84, 4, SS), 256, smem2>>>();
    k3_lstm<<<SS*4, 1024, smem3>>>(Wlin, blin, out);
}